// round 10
// baseline (speedup 1.0000x reference)
#include <cuda_runtime.h>
#include <cuda_fp16.h>
#include <cstdint>

#define N_NODES   131072
#define NUM_LAYERS 4
#define NUM_EQ    1024
#define TILE_M    256
#define NUM_TILES (N_NODES / TILE_M)     // 512
#define SCALE 64.0f

// smem map: [0..4096) nbr ids (1024) + mbarW @3968 | [4096..135168) W0 subs
// [135168..167936) A buf0 | [167936..200704) A buf1
#define WS_OFF   4096
#define RB_OFF   (WS_OFF + 131072)
#define SMEM_BYTES (RB_OFF + 2 * 32768)

// ---------------- static device buffers (no allocs allowed) ----------------
__device__ __align__(16) __half g_f0[N_NODES * 128];
__device__ __align__(16) __half g_f1[N_NODES * 128];
// W0 blob: [layer][sub 0..7][128 n-rows x 64 k fp16, ldsm-swizzled] (16KB/sub)
__device__ __align__(16) __half g_wblob[NUM_LAYERS * 8 * 8192];
// W1 fragments (GEMM2): [layer][sub 0..1][wx 0..1][512 uint4] per-lane mma order
__device__ __align__(16) uint4 g_wfrag[NUM_LAYERS * 2 * 2 * 512];

// ---------------- helpers ----------------
__device__ __forceinline__ uint32_t smem_u32(const void* p) {
    uint32_t a;
    asm("{ .reg .u64 t; cvta.to.shared.u64 t, %1; cvt.u32.u64 %0, t; }"
        : "=r"(a) : "l"(p));
    return a;
}
#define CP16(dst, src, sz) \
    asm volatile("cp.async.cg.shared.global [%0], [%1], 16, %2;" \
                 :: "r"(dst), "l"(src), "r"(sz) : "memory")
#define CPCOMMIT() asm volatile("cp.async.commit_group;" ::: "memory")
#define CPWAIT0()  asm volatile("cp.async.wait_group 0;" ::: "memory")
#define MBARRIER_INIT(addr, cnt) \
    asm volatile("mbarrier.init.shared.b64 [%0], %1;" :: "r"(addr), "r"(cnt) : "memory")
#define MBARRIER_EXPECT_TX(addr, bytes) \
    asm volatile("mbarrier.arrive.expect_tx.shared.b64 _, [%0], %1;" \
                 :: "r"(addr), "r"(bytes) : "memory")
#define MBARRIER_WAIT_PARITY(addr, par) do {                                      \
    uint32_t _m = (uint32_t)(addr); uint32_t _p = (uint32_t)(par); uint32_t _d;   \
    asm volatile("{ .reg .pred p;"                                                \
        " mbarrier.try_wait.parity.acquire.cta.shared::cta.b64 p, [%1], %2;"      \
        " selp.b32 %0, 1, 0, p; }" : "=r"(_d) : "r"(_m), "r"(_p) : "memory");     \
    if (!_d) {                                                                    \
        asm volatile("{ .reg .pred P1;"                                           \
        " WL_%=:"                                                                 \
        " mbarrier.try_wait.parity.acquire.cta.shared::cta.b64 P1, [%0], %1, 0x989680;" \
        " @P1 bra.uni WD_%=;"                                                     \
        " bra.uni WL_%=;"                                                         \
        " WD_%=: }" :: "r"(_m), "r"(_p) : "memory");                              \
    }                                                                             \
} while (0)
#define BULK_G2S(dst, src, sz, mbar) \
    asm volatile("cp.async.bulk.shared::cluster.global.mbarrier::complete_tx::bytes " \
                 "[%0], [%1], %2, [%3];" \
                 :: "r"(dst), "l"(src), "r"(sz), "r"(mbar) : "memory")

__device__ __forceinline__ void ldsm4(uint32_t* r, uint32_t addr) {
    asm volatile("ldmatrix.sync.aligned.m8n8.x4.shared.b16 {%0,%1,%2,%3}, [%4];"
                 : "=r"(r[0]), "=r"(r[1]), "=r"(r[2]), "=r"(r[3]) : "r"(addr));
}
__device__ __forceinline__ void hmma(float* d, const uint32_t* a,
                                     uint32_t b0, uint32_t b1) {
    asm volatile(
        "mma.sync.aligned.m16n8k16.row.col.f32.f16.f16.f32 "
        "{%0,%1,%2,%3}, {%4,%5,%6,%7}, {%8,%9}, {%0,%1,%2,%3};"
        : "+f"(d[0]), "+f"(d[1]), "+f"(d[2]), "+f"(d[3])
        : "r"(a[0]), "r"(a[1]), "r"(a[2]), "r"(a[3]), "r"(b0), "r"(b1));
}
// tile: rows x 64 k fp16 (128B rows, 8x16B chunks), XOR swizzle for ldsm
__device__ __forceinline__ uint32_t tadr(uint32_t base, int row, int ck) {
    return base + row * 128 + (((uint32_t)ck ^ (row & 7)) << 4);
}

// ---------------------------------------------------------------------------
// prep: W0 -> transposed ldsm-swizzled sub-tiles; W1 -> per-lane fragments
// ---------------------------------------------------------------------------
__global__ void prep_w(const float* __restrict__ W0) {
    int i = blockIdx.x * blockDim.x + threadIdx.x;
    if (i >= NUM_LAYERS * 8 * 8192) return;
    int e   = i & 8191;
    int sub = (i >> 13) & 7;
    int l   = i >> 16;
    int n   = e >> 6;             // N row 0..127
    int kk  = e & 63;             // K within subtile
    float w = W0[((size_t)l * 512 + sub * 64 + kk) * 128 + n];
    int ck = kk >> 3;
    uint32_t sw = (uint32_t)(n * 128) + (((uint32_t)ck ^ (n & 7)) << 4) + (kk & 7) * 2;
    *reinterpret_cast<__half*>(
        reinterpret_cast<char*>(g_wblob) + (size_t)(i - e) * 2 + sw) = __float2half_rn(w);
}
__global__ void prep_w1(const float* __restrict__ W1) {
    int i = blockIdx.x * blockDim.x + threadIdx.x;   // word index
    if (i >= NUM_LAYERS * 2 * 2 * 2048) return;
    int w    = i & 3;
    int lane = (i >> 2) & 31;
    int g    = (i >> 7) & 3;
    int ks   = (i >> 9) & 3;
    int wx   = (i >> 11) & 1;
    int sub  = (i >> 12) & 1;
    int l    = i >> 13;
    int n = wx * 64 + g * 16 + ((w >> 1) << 3) + (lane >> 2);
    int k = ks * 16 + ((w & 1) << 3) + (lane & 3) * 2;
    const float* base = W1 + ((size_t)l * 128 + sub * 64 + k) * 128 + n;
    __half2 p = __floats2half2_rn(base[0], base[128]);
    reinterpret_cast<uint32_t*>(g_wfrag)[i] = *reinterpret_cast<uint32_t*>(&p);
}

// ---------------------------------------------------------------------------
// embed: feats = SCALE * emb[node_idx]  -> fp16 into buffer 0
// ---------------------------------------------------------------------------
__global__ void embed_k(const int* __restrict__ node_idx, const float* __restrict__ emb) {
    int i = blockIdx.x * blockDim.x + threadIdx.x;
    if (i >= N_NODES * 32) return;
    int n  = i >> 5;
    int c4 = i & 31;
    float4 vv = reinterpret_cast<const float4*>(emb)[node_idx[n] * 32 + c4];
    __half2 p0 = __floats2half2_rn(vv.x * SCALE, vv.y * SCALE);
    __half2 p1 = __floats2half2_rn(vv.z * SCALE, vv.w * SCALE);
    reinterpret_cast<uint2*>(g_f0)[i] =
        make_uint2(*reinterpret_cast<uint32_t*>(&p0), *reinterpret_cast<uint32_t*>(&p1));
}

// ---------------------------------------------------------------------------
// compute: A from smem tile, B from smem weight sub-tile (both ldsm)
// ---------------------------------------------------------------------------
__device__ __forceinline__ void computeWS(float acc[2][8][4], uint32_t bufA,
                                          uint32_t bufB, int lane, int wy, int wx) {
    const int rsel = lane & 15;
    const int hi   = lane >> 4;
    #pragma unroll
    for (int ks = 0; ks < 4; ks++) {
        const int csel = 2 * ks + hi;
        uint32_t a[2][4];
        #pragma unroll
        for (int mi = 0; mi < 2; mi++)
            ldsm4(a[mi], tadr(bufA, wy * 32 + mi * 16 + rsel, csel));
        #pragma unroll
        for (int g = 0; g < 4; g++) {
            uint32_t b[4];
            ldsm4(b, tadr(bufB, wx * 64 + g * 16 + rsel, csel));
            #pragma unroll
            for (int mi = 0; mi < 2; mi++) {
                hmma(acc[mi][2 * g],     a[mi], b[0], b[2]);
                hmma(acc[mi][2 * g + 1], a[mi], b[1], b[3]);
            }
        }
    }
}
// compute: A from smem tile, B from global fragment blob (LDG)
__device__ __forceinline__ void computeWF(float acc[2][8][4], uint32_t bufA,
                                          const uint4* __restrict__ wsub,
                                          int lane, int wy) {
    const int rsel = lane & 15;
    const int hi   = lane >> 4;
    #pragma unroll
    for (int ks = 0; ks < 4; ks++) {
        uint32_t a[2][4];
        #pragma unroll
        for (int mi = 0; mi < 2; mi++)
            ldsm4(a[mi], tadr(bufA, wy * 32 + mi * 16 + rsel, 2 * ks + hi));
        #pragma unroll
        for (int g = 0; g < 4; g++) {
            uint4 q = wsub[(ks * 4 + g) * 32 + lane];
            #pragma unroll
            for (int mi = 0; mi < 2; mi++) {
                hmma(acc[mi][2 * g],     a[mi], q.x, q.y);
                hmma(acc[mi][2 * g + 1], a[mi], q.z, q.w);
            }
        }
    }
}

__global__ __launch_bounds__(512, 1)
void layer_k(int l, int srcBuf, const int* __restrict__ neighbors,
             const float* __restrict__ b0, const float* __restrict__ b1) {
    extern __shared__ __align__(128) char smem[];
    int* sNbr = (int*)smem;
    const uint32_t sb = smem_u32(smem);
    const uint32_t MBW  = sb + 3968;               // W-load mbarrier
    const uint32_t WS   = sb + WS_OFF;             // 8 x 16KB W0 subs
    const uint32_t RB0  = sb + RB_OFF, RB1 = RB0 + 32768;

    const int tid = threadIdx.x, lane = tid & 31, wid = tid >> 5;
    const int wy = wid >> 1, wx = wid & 1;         // 8 x 2 warp grid (32x64 tiles)

    const __half* fin = srcBuf ? g_f1 : g_f0;
    __half* fout      = srcBuf ? g_f0 : g_f1;

    sNbr[tid]       = neighbors[blockIdx.x * 1024 + tid];
    sNbr[tid + 512] = neighbors[blockIdx.x * 1024 + 512 + tid];
    if (tid == 0) {
        MBARRIER_INIT(MBW, 1);
        MBARRIER_EXPECT_TX(MBW, 131072u);
        BULK_G2S(WS, reinterpret_cast<const char*>(g_wblob) + (size_t)l * 131072,
                 131072u, MBW);                    // whole W0 for this layer
    }
    __syncthreads();

    const char* finB = reinterpret_cast<const char*>(fin);

    // one K=64 A-gather stage (zfill for pad node): 2048 chunks, 4/thread
    auto issue = [&](int s) {
        const uint32_t buf = (s & 1) ? RB1 : RB0;
        const int j = s >> 1, half = s & 1;
        #pragma unroll
        for (int r = 0; r < 4; r++) {
            int c = tid + 512 * r;                 // 0..2047
            int row = c >> 3, ck = c & 7;
            int sn = sNbr[row * 4 + j];
            uint32_t sz = (sn == N_NODES) ? 0u : 16u;
            size_t so = (size_t)sn * 256 + half * 128 + ck * 16;
            CP16(tadr(buf, row, ck), finB + so, sz);
        }
    };

    float acc[2][8][4];
    #pragma unroll
    for (int mi = 0; mi < 2; mi++)
        #pragma unroll
        for (int ni = 0; ni < 8; ni++)
            #pragma unroll
            for (int q = 0; q < 4; q++) acc[mi][ni][q] = 0.f;

    // -------- GEMM1: gathered[256x512] @ W0, 8 K=64 stages, ring-2 --------
    issue(0); CPCOMMIT();
    #pragma unroll 1
    for (int s = 0; s < 8; s++) {
        CPWAIT0();                       // A stage s landed
        __syncthreads();                 // visible to all; compute(s-1) done
        if (s < 7) { issue(s + 1); CPCOMMIT(); }   // fill the other buffer
        if (s == 0) { MBARRIER_WAIT_PARITY(MBW, 0); }  // W0 resident
        computeWS(acc, (s & 1) ? RB1 : RB0, WS + (uint32_t)s * 16384, lane, wy, wx);
    }
    __syncthreads();                     // all warps done reading A ring

    // -------- epilogue1: H = relu(acc + s*b0) -> fp16 into ring bufs ----
    // wx=0 warps produce GEMM2-K 0..63 -> RB0; wx=1 -> K 64..127 -> RB1
    const uint32_t hbuf = wx ? RB1 : RB0;
    #pragma unroll
    for (int mi = 0; mi < 2; mi++) {
        #pragma unroll
        for (int ni = 0; ni < 8; ni++) {
            int kl = ni * 8 + (lane & 3) * 2;      // k within GEMM2 subtile
            int ncol = wx * 64 + kl;               // GEMM1 output column
            float bb0 = __ldg(&b0[ncol]) * SCALE;
            float bb1 = __ldg(&b0[ncol + 1]) * SCALE;
            #pragma unroll
            for (int h = 0; h < 2; h++) {
                int row = wy * 32 + mi * 16 + (lane >> 2) + h * 8;
                float x0 = acc[mi][ni][2 * h]     + bb0;
                float x1 = acc[mi][ni][2 * h + 1] + bb1;
                x0 = x0 > 0.f ? x0 : 0.f;
                x1 = x1 > 0.f ? x1 : 0.f;
                __half2 p = __floats2half2_rn(x0, x1);
                uint32_t a = tadr(hbuf, row, kl >> 3) + (kl & 7) * 2;
                asm volatile("st.shared.b32 [%0], %1;"
                             :: "r"(a), "r"(*reinterpret_cast<uint32_t*>(&p)) : "memory");
            }
        }
    }
    __syncthreads();                     // H visible to all warps

    // -------- GEMM2: H[256x128] @ W1 (frag LDG), 2 K=64 stages --------
    #pragma unroll
    for (int mi = 0; mi < 2; mi++)
        #pragma unroll
        for (int ni = 0; ni < 8; ni++)
            #pragma unroll
            for (int q = 0; q < 4; q++) acc[mi][ni][q] = 0.f;
    const uint4* f8 = g_wfrag + ((size_t)(l * 2 + 0) * 2 + wx) * 512;
    const uint4* f9 = g_wfrag + ((size_t)(l * 2 + 1) * 2 + wx) * 512;
    computeWF(acc, RB0, f8, lane, wy);
    computeWF(acc, RB1, f9, lane, wy);

    // -------- epilogue2: out = acc + s*b1 -> fp16 to global --------
    #pragma unroll
    for (int mi = 0; mi < 2; mi++) {
        #pragma unroll
        for (int ni = 0; ni < 8; ni++) {
            int ncol = wx * 64 + ni * 8 + (lane & 3) * 2;
            float bb0 = __ldg(&b1[ncol]) * SCALE;
            float bb1 = __ldg(&b1[ncol + 1]) * SCALE;
            #pragma unroll
            for (int h = 0; h < 2; h++) {
                int row = wy * 32 + mi * 16 + (lane >> 2) + h * 8;
                size_t gOff = (size_t)(blockIdx.x * TILE_M + row) * 128 + ncol;
                __half2 p = __floats2half2_rn(acc[mi][ni][2 * h] + bb0,
                                              acc[mi][ni][2 * h + 1] + bb1);
                *reinterpret_cast<uint32_t*>(fout + gOff) =
                    *reinterpret_cast<uint32_t*>(&p);
            }
        }
    }
}

// ---------------------------------------------------------------------------
// readout: logits[b] = dot(meanL, meanR)/s^2 + out_bias  (feats in g_f0)
// ---------------------------------------------------------------------------
__global__ void readout_k(const float* __restrict__ out_bias, float* __restrict__ logits) {
    const int b = blockIdx.x;
    const int t = threadIdx.x;   // 0..127
    size_t baseL = (size_t)(2 * b) * 64 * 128;
    size_t baseR = baseL + 64 * 128;
    float sl = 0.f, sr = 0.f;
    #pragma unroll 8
    for (int i = 0; i < 64; i++) {
        sl += __half2float(g_f0[baseL + i * 128 + t]);
        sr += __half2float(g_f0[baseR + i * 128 + t]);
    }
    float v = sl * sr;
    #pragma unroll
    for (int o = 16; o > 0; o >>= 1) v += __shfl_down_sync(0xffffffffu, v, o);
    __shared__ float red[4];
    if ((t & 31) == 0) red[t >> 5] = v;
    __syncthreads();
    if (t == 0)
        logits[b] = (red[0] + red[1] + red[2] + red[3]) *
                    (1.f / (4096.f * SCALE * SCALE)) + out_bias[0];
}

// ---------------------------------------------------------------------------
extern "C" void kernel_launch(void* const* d_in, const int* in_sizes, int n_in,
                              void* d_out, int out_size) {
    const int*   node_idx  = (const int*)  d_in[0];
    const int*   neighbors = (const int*)  d_in[1];
    const float* emb       = (const float*)d_in[3];
    const float* W0        = (const float*)d_in[4];
    const float* b0        = (const float*)d_in[5];
    const float* W1        = (const float*)d_in[6];
    const float* b1        = (const float*)d_in[7];
    const float* out_bias  = (const float*)d_in[8];
    float* logits = (float*)d_out;

    cudaFuncSetAttribute(layer_k, cudaFuncAttributeMaxDynamicSharedMemorySize, SMEM_BYTES);

    {
        int total = NUM_LAYERS * 8 * 8192;
        prep_w<<<(total + 255) / 256, 256>>>(W0);
    }
    {
        int total = NUM_LAYERS * 2 * 2 * 2048;
        prep_w1<<<(total + 255) / 256, 256>>>(W1);
    }
    {
        int total = N_NODES * 32;
        embed_k<<<(total + 255) / 256, 256>>>(node_idx, emb);
    }
    for (int l = 0; l < NUM_LAYERS; l++) {
        layer_k<<<NUM_TILES, 512, SMEM_BYTES>>>(
            l, l & 1, neighbors,
            b0 + (size_t)l * 128,
            b1 + (size_t)l * 128);
    }
    readout_k<<<NUM_EQ, 128>>>(out_bias, logits);
}

// round 12
// speedup vs baseline: 1.2535x; 1.2535x over previous
#include <cuda_runtime.h>
#include <cuda_fp16.h>
#include <cstdint>

#define N_NODES   131072
#define NUM_LAYERS 4
#define NUM_EQ    1024
#define NUM_TILES 1024
#define SCALE 64.0f

// smem: [0..2048) nbr ids, [2048..2088) 5 mbarriers, [4096..) 3 x 32KB stages
// stage layout: A 16K | B 16K
#define SMEM_BYTES (4096 + 3 * 32768)

// ---------------- static device buffers (no allocs allowed) ----------------
__device__ __align__(16) __half g_f0[N_NODES * 128];
__device__ __align__(16) __half g_f1[N_NODES * 128];
// weight blobs: [layer][sub 0..9][128 n-rows x 64 k fp16, ldsm-swizzled] 16KB/sub
// sub 0..7 -> W0 K-chunks (K=512), sub 8..9 -> W1 K-chunks (K=128)
__device__ __align__(16) __half g_wblob[NUM_LAYERS * 10 * 8192];

// ---------------- helpers ----------------
__device__ __forceinline__ uint32_t smem_u32(const void* p) {
    uint32_t a;
    asm("{ .reg .u64 t; cvta.to.shared.u64 t, %1; cvt.u32.u64 %0, t; }"
        : "=r"(a) : "l"(p));
    return a;
}
#define CP16(dst, src, sz) \
    asm volatile("cp.async.cg.shared.global [%0], [%1], 16, %2;" \
                 :: "r"(dst), "l"(src), "r"(sz) : "memory")
#define CPCOMMIT() asm volatile("cp.async.commit_group;" ::: "memory")
#define CPWAIT0()  asm volatile("cp.async.wait_group 0;" ::: "memory")
#define CPWAIT1()  asm volatile("cp.async.wait_group 1;" ::: "memory")
#define MBARRIER_INIT(addr, cnt) \
    asm volatile("mbarrier.init.shared.b64 [%0], %1;" :: "r"(addr), "r"(cnt) : "memory")
#define MBARRIER_EXPECT_TX(addr, bytes) \
    asm volatile("mbarrier.arrive.expect_tx.shared.b64 _, [%0], %1;" \
                 :: "r"(addr), "r"(bytes) : "memory")
#define MBARRIER_WAIT_PARITY(addr, par) do {                                      \
    uint32_t _m = (uint32_t)(addr); uint32_t _p = (uint32_t)(par); uint32_t _d;   \
    asm volatile("{ .reg .pred p;"                                                \
        " mbarrier.try_wait.parity.acquire.cta.shared::cta.b64 p, [%1], %2;"      \
        " selp.b32 %0, 1, 0, p; }" : "=r"(_d) : "r"(_m), "r"(_p) : "memory");     \
    if (!_d) {                                                                    \
        asm volatile("{ .reg .pred P1;"                                           \
        " WL_%=:"                                                                 \
        " mbarrier.try_wait.parity.acquire.cta.shared::cta.b64 P1, [%0], %1, 0x989680;" \
        " @P1 bra.uni WD_%=;"                                                     \
        " bra.uni WL_%=;"                                                         \
        " WD_%=: }" :: "r"(_m), "r"(_p) : "memory");                              \
    }                                                                             \
} while (0)
#define BULK_G2S(dst, src, sz, mbar) \
    asm volatile("cp.async.bulk.shared::cluster.global.mbarrier::complete_tx::bytes " \
                 "[%0], [%1], %2, [%3];" \
                 :: "r"(dst), "l"(src), "r"(sz), "r"(mbar) : "memory")

__device__ __forceinline__ void ldsm4(uint32_t* r, uint32_t addr) {
    asm volatile("ldmatrix.sync.aligned.m8n8.x4.shared.b16 {%0,%1,%2,%3}, [%4];"
                 : "=r"(r[0]), "=r"(r[1]), "=r"(r[2]), "=r"(r[3]) : "r"(addr));
}
__device__ __forceinline__ void hmma(float* d, const uint32_t* a,
                                     uint32_t b0, uint32_t b1) {
    asm volatile(
        "mma.sync.aligned.m16n8k16.row.col.f32.f16.f16.f32 "
        "{%0,%1,%2,%3}, {%4,%5,%6,%7}, {%8,%9}, {%0,%1,%2,%3};"
        : "+f"(d[0]), "+f"(d[1]), "+f"(d[2]), "+f"(d[3])
        : "r"(a[0]), "r"(a[1]), "r"(a[2]), "r"(a[3]), "r"(b0), "r"(b1));
}
// tile: 128 rows x 64 k fp16 (128B rows, 8x16B chunks), XOR swizzle for ldsm
__device__ __forceinline__ uint32_t tadr(uint32_t base, int row, int ck) {
    return base + row * 128 + (((uint32_t)ck ^ (row & 7)) << 4);
}

// ---------------------------------------------------------------------------
// prep: transposed, ldsm-swizzled fp16 weight blobs (bulk-copy-ready images)
// ---------------------------------------------------------------------------
__global__ void prep_w(const float* __restrict__ W0, const float* __restrict__ W1) {
    int i = blockIdx.x * blockDim.x + threadIdx.x;
    if (i >= NUM_LAYERS * 10 * 8192) return;
    int e   = i & 8191;
    int g   = i >> 13;            // l*10 + sub
    int sub = g % 10;
    int l   = g / 10;
    int n   = e >> 6;             // N row 0..127
    int kk  = e & 63;             // K within subtile
    float w;
    if (sub < 8) w = W0[((size_t)l * 512 + sub * 64 + kk) * 128 + n];
    else         w = W1[((size_t)l * 128 + (sub - 8) * 64 + kk) * 128 + n];
    int ck = kk >> 3;
    uint32_t sw = (uint32_t)(n * 128) + (((uint32_t)ck ^ (n & 7)) << 4) + (kk & 7) * 2;
    *reinterpret_cast<__half*>(
        reinterpret_cast<char*>(g_wblob) + (size_t)(i - e) * 2 + sw) = __float2half_rn(w);
}

// ---------------------------------------------------------------------------
// embed: feats = SCALE * emb[node_idx]  -> fp16 into buffer 0
// ---------------------------------------------------------------------------
__global__ void embed_k(const int* __restrict__ node_idx, const float* __restrict__ emb) {
    int i = blockIdx.x * blockDim.x + threadIdx.x;
    if (i >= N_NODES * 32) return;
    int n  = i >> 5;
    int c4 = i & 31;
    float4 vv = reinterpret_cast<const float4*>(emb)[node_idx[n] * 32 + c4];
    __half2 p0 = __floats2half2_rn(vv.x * SCALE, vv.y * SCALE);
    __half2 p1 = __floats2half2_rn(vv.z * SCALE, vv.w * SCALE);
    reinterpret_cast<uint2*>(g_f0)[i] =
        make_uint2(*reinterpret_cast<uint32_t*>(&p0), *reinterpret_cast<uint32_t*>(&p1));
}

// ---------------------------------------------------------------------------
// fused layer: fp16 HMMA; A via cp.async (LSU), B via cp.async.bulk (TMA)
// ---------------------------------------------------------------------------
__device__ __forceinline__ void compute64(float acc[2][8][4], uint32_t buf,
                                          int lane, int wy, int wx) {
    const int rsel = lane & 15;
    const int hi   = lane >> 4;
    #pragma unroll
    for (int ks = 0; ks < 4; ks++) {
        const int csel = 2 * ks + hi;
        uint32_t a[2][4];
        #pragma unroll
        for (int mi = 0; mi < 2; mi++)
            ldsm4(a[mi], tadr(buf, wy * 32 + mi * 16 + rsel, csel));
        #pragma unroll
        for (int g = 0; g < 4; g++) {
            uint32_t b[4];
            ldsm4(b, tadr(buf + 16384, wx * 64 + g * 16 + rsel, csel));
            #pragma unroll
            for (int mi = 0; mi < 2; mi++) {
                hmma(acc[mi][2 * g],     a[mi], b[0], b[2]);
                hmma(acc[mi][2 * g + 1], a[mi], b[1], b[3]);
            }
        }
    }
}

__global__ __launch_bounds__(256, 2)
void layer_k(int l, int srcBuf, const int* __restrict__ neighbors,
             const float* __restrict__ b0, const float* __restrict__ b1) {
    extern __shared__ __align__(128) char smem[];
    int* sNbr = (int*)smem;
    const uint32_t sb   = smem_u32(smem);
    const uint32_t MBAR = sb + 2048;     // 3 stage mbars + 2 W1 mbars
    const uint32_t BUF0 = sb + 4096;

    const int tid = threadIdx.x, lane = tid & 31, wid = tid >> 5;
    const int wy = wid >> 1, wx = wid & 1;

    const __half* fin = srcBuf ? g_f1 : g_f0;
    __half* fout      = srcBuf ? g_f0 : g_f1;

    sNbr[tid]       = neighbors[blockIdx.x * 512 + tid];
    sNbr[tid + 256] = neighbors[blockIdx.x * 512 + 256 + tid];
    if (tid == 0) {
        MBARRIER_INIT(MBAR + 0, 1);
        MBARRIER_INIT(MBAR + 8, 1);
        MBARRIER_INIT(MBAR + 16, 1);
        MBARRIER_INIT(MBAR + 24, 1);   // W1 sub8
        MBARRIER_INIT(MBAR + 32, 1);   // W1 sub9
    }
    __syncthreads();

    const char* finB  = reinterpret_cast<const char*>(fin);
    const char* blobB = reinterpret_cast<const char*>(g_wblob);

    // A gather for one K=64 stage (zfill for pad node): 4 cp.async / thread
    auto issueA = [&](int s) {
        const uint32_t buf = BUF0 + (s % 3) * 32768;
        const int j = s >> 1, half = s & 1;
        #pragma unroll
        for (int r = 0; r < 4; r++) {
            int c = tid + 256 * r;                 // 0..1023
            int row = c >> 3, ck = c & 7;
            int sn = sNbr[row * 4 + j];
            uint32_t sz = (sn == N_NODES) ? 0u : 16u;
            size_t so = (size_t)sn * 256 + half * 128 + ck * 16;
            CP16(tadr(buf, row, ck), finB + so, sz);
        }
    };
    // B weights for one stage: single 16KB bulk on the stage's mbarrier (tid 0)
    auto issueB = [&](int s) {
        const uint32_t buf  = BUF0 + (s % 3) * 32768;
        const uint32_t mbar = MBAR + (s % 3) * 8;
        MBARRIER_EXPECT_TX(mbar, 16384u);
        BULK_G2S(buf + 16384, blobB + (size_t)(l * 10 + s) * 16384, 16384u, mbar);
    };
    // W1 prefetch on dedicated mbars: q=0 sub8 -> buf2.B, q=1 sub9 -> buf0.B
    auto issueW1 = [&](int q) {
        const uint32_t buf  = BUF0 + (q ? 0 : 2) * 32768;
        const uint32_t mbar = MBAR + 24 + q * 8;
        MBARRIER_EXPECT_TX(mbar, 16384u);
        BULK_G2S(buf + 16384, blobB + (size_t)(l * 10 + 8 + q) * 16384, 16384u, mbar);
    };

    float acc[2][8][4];
    #pragma unroll
    for (int mi = 0; mi < 2; mi++)
        #pragma unroll
        for (int ni = 0; ni < 8; ni++)
            #pragma unroll
            for (int q = 0; q < 4; q++) acc[mi][ni][q] = 0.f;

    // -------- GEMM1: gathered[128x512] @ W0, 8 K=64 stages, ring-3 --------
    issueA(0); CPCOMMIT();
    issueA(1); CPCOMMIT();
    if (tid == 0) { issueB(0); issueB(1); }
    #pragma unroll 1
    for (int s = 0; s < 8; s++) {
        if (s < 7) { CPWAIT1(); } else { CPWAIT0(); }   // A of stage s landed
        __syncthreads();                 // visible to all; compute(s-1) done
        if (s < 6) {
            issueA(s + 2); CPCOMMIT();               // into buf (s-1)%3, now free
            if (tid == 0) issueB(s + 2);
        } else if (tid == 0) {
            issueW1(s - 6);              // s=6: sub8->buf2.B, s=7: sub9->buf0.B
        }
        MBARRIER_WAIT_PARITY(MBAR + (s % 3) * 8, (s / 3) & 1);   // B of stage s
        compute64(acc, BUF0 + (s % 3) * 32768, lane, wy, wx);
    }
    __syncthreads();                     // all computes done

    // -------- epilogue1: H = relu(acc + s*b0) -> fp16 into A regions ----
    // wx=0 -> GEMM2-K 0..63 -> buf2.A (pairs W1 sub8); wx=1 -> 64..127 -> buf0.A
    const uint32_t hbuf = wx ? (BUF0 + 0 * 32768) : (BUF0 + 2 * 32768);
    #pragma unroll
    for (int mi = 0; mi < 2; mi++) {
        #pragma unroll
        for (int ni = 0; ni < 8; ni++) {
            int kl = ni * 8 + (lane & 3) * 2;      // k within GEMM2 subtile
            int ncol = wx * 64 + kl;               // GEMM1 output column
            float bb0 = __ldg(&b0[ncol]) * SCALE;
            float bb1 = __ldg(&b0[ncol + 1]) * SCALE;
            #pragma unroll
            for (int h = 0; h < 2; h++) {
                int row = wy * 32 + mi * 16 + (lane >> 2) + h * 8;
                float x0 = acc[mi][ni][2 * h]     + bb0;
                float x1 = acc[mi][ni][2 * h + 1] + bb1;
                x0 = x0 > 0.f ? x0 : 0.f;
                x1 = x1 > 0.f ? x1 : 0.f;
                __half2 p = __floats2half2_rn(x0, x1);
                uint32_t a = tadr(hbuf, row, kl >> 3) + (kl & 7) * 2;
                asm volatile("st.shared.b32 [%0], %1;"
                             :: "r"(a), "r"(*reinterpret_cast<uint32_t*>(&p)) : "memory");
            }
        }
    }
    __syncthreads();                     // H visible to all warps

    // -------- GEMM2: H[128x128] @ W1, 2 K=64 stages --------
    #pragma unroll
    for (int mi = 0; mi < 2; mi++)
        #pragma unroll
        for (int ni = 0; ni < 8; ni++)
            #pragma unroll
            for (int q = 0; q < 4; q++) acc[mi][ni][q] = 0.f;
    MBARRIER_WAIT_PARITY(MBAR + 24, 0);  // W1 sub8 in buf2.B
    compute64(acc, BUF0 + 2 * 32768, lane, wy, wx);
    MBARRIER_WAIT_PARITY(MBAR + 32, 0);  // W1 sub9 in buf0.B
    compute64(acc, BUF0 + 0 * 32768, lane, wy, wx);

    // -------- epilogue2: out = acc + s*b1 -> fp16 to global --------
    #pragma unroll
    for (int mi = 0; mi < 2; mi++) {
        #pragma unroll
        for (int ni = 0; ni < 8; ni++) {
            int ncol = wx * 64 + ni * 8 + (lane & 3) * 2;
            float bb0 = __ldg(&b1[ncol]) * SCALE;
            float bb1 = __ldg(&b1[ncol + 1]) * SCALE;
            #pragma unroll
            for (int h = 0; h < 2; h++) {
                int row = wy * 32 + mi * 16 + (lane >> 2) + h * 8;
                size_t gOff = (size_t)(blockIdx.x * 128 + row) * 128 + ncol;
                __half2 p = __floats2half2_rn(acc[mi][ni][2 * h] + bb0,
                                              acc[mi][ni][2 * h + 1] + bb1);
                *reinterpret_cast<uint32_t*>(fout + gOff) =
                    *reinterpret_cast<uint32_t*>(&p);
            }
        }
    }
}

// ---------------------------------------------------------------------------
// readout: logits[b] = dot(meanL, meanR)/s^2 + out_bias  (feats in g_f0)
// ---------------------------------------------------------------------------
__global__ void readout_k(const float* __restrict__ out_bias, float* __restrict__ logits) {
    const int b = blockIdx.x;
    const int t = threadIdx.x;   // 0..127
    size_t baseL = (size_t)(2 * b) * 64 * 128;
    size_t baseR = baseL + 64 * 128;
    float sl = 0.f, sr = 0.f;
    #pragma unroll 8
    for (int i = 0; i < 64; i++) {
        sl += __half2float(g_f0[baseL + i * 128 + t]);
        sr += __half2float(g_f0[baseR + i * 128 + t]);
    }
    float v = sl * sr;
    #pragma unroll
    for (int o = 16; o > 0; o >>= 1) v += __shfl_down_sync(0xffffffffu, v, o);
    __shared__ float red[4];
    if ((t & 31) == 0) red[t >> 5] = v;
    __syncthreads();
    if (t == 0)
        logits[b] = (red[0] + red[1] + red[2] + red[3]) *
                    (1.f / (4096.f * SCALE * SCALE)) + out_bias[0];
}

// ---------------------------------------------------------------------------
extern "C" void kernel_launch(void* const* d_in, const int* in_sizes, int n_in,
                              void* d_out, int out_size) {
    const int*   node_idx  = (const int*)  d_in[0];
    const int*   neighbors = (const int*)  d_in[1];
    const float* emb       = (const float*)d_in[3];
    const float* W0        = (const float*)d_in[4];
    const float* b0        = (const float*)d_in[5];
    const float* W1        = (const float*)d_in[6];
    const float* b1        = (const float*)d_in[7];
    const float* out_bias  = (const float*)d_in[8];
    float* logits = (float*)d_out;

    cudaFuncSetAttribute(layer_k, cudaFuncAttributeMaxDynamicSharedMemorySize, SMEM_BYTES);

    {
        int total = NUM_LAYERS * 10 * 8192;
        prep_w<<<(total + 255) / 256, 256>>>(W0, W1);
    }
    {
        int total = N_NODES * 32;
        embed_k<<<(total + 255) / 256, 256>>>(node_idx, emb);
    }
    for (int l = 0; l < NUM_LAYERS; l++) {
        layer_k<<<NUM_TILES, 256, SMEM_BYTES>>>(
            l, l & 1, neighbors,
            b0 + (size_t)l * 128,
            b1 + (size_t)l * 128);
    }
    readout_k<<<NUM_EQ, 128>>>(out_bias, logits);
}